// round 9
// baseline (speedup 1.0000x reference)
#include <cuda_runtime.h>
#include <cuda_fp16.h>
#include <math.h>

#define N_NODES 1048576
#define N_EDGES 4194304
#define EPSV 1e-5f
#define STATS_LEN (7*24 + 3*12)

// ---------------- scratch (static device globals; zero-init at load) ----------------
__device__ float  g_hA[N_NODES * 12];
__device__ float  g_hB[N_NODES * 12];
__device__ __half g_hHA[N_NODES * 16];   // fp16 mirror (32B rows) for gather
__device__ __half g_hHB[N_NODES * 16];
__device__ float4 g_xp[N_NODES];         // x packed to float4
__device__ int    g_deg[N_NODES];        // zeroed by k_scanA for next call
__device__ int    g_off[N_NODES + 1];
__device__ int    g_cur[N_NODES];
__device__ int    g_bsum[1024];
__device__ int    g_srt[N_EDGES];        // src ids grouped by dst (CSR adjacency)
__device__ float  g_stats[STATS_LEN];    // zeroed by k_scanB for next call

__device__ __forceinline__ float*  bufptr(int s)  { return s == 0 ? g_hA : g_hB; }
__device__ __forceinline__ __half* bufptrH(int s) { return s == 0 ? g_hHA : g_hHB; }

__device__ __forceinline__ void warpsum(float& v) {
#pragma unroll
    for (int o = 16; o; o >>= 1) v += __shfl_xor_sync(0xffffffffu, v, o);
}

// accumulate one fp16 row given preloaded raw words
__device__ __forceinline__ void accH(float* acc, uint4 a, uint2 b) {
    float2 f;
    f = __half22float2(*reinterpret_cast<__half2*>(&a.x)); acc[0] += f.x; acc[1] += f.y;
    f = __half22float2(*reinterpret_cast<__half2*>(&a.y)); acc[2] += f.x; acc[3] += f.y;
    f = __half22float2(*reinterpret_cast<__half2*>(&a.z)); acc[4] += f.x; acc[5] += f.y;
    f = __half22float2(*reinterpret_cast<__half2*>(&a.w)); acc[6] += f.x; acc[7] += f.y;
    f = __half22float2(*reinterpret_cast<__half2*>(&b.x)); acc[8] += f.x; acc[9] += f.y;
    f = __half22float2(*reinterpret_cast<__half2*>(&b.y)); acc[10] += f.x; acc[11] += f.y;
}

__device__ __forceinline__ void storeH(__half* hH, int i, const float* out) {
    __half* r = hH + ((size_t)i << 4);
    uint4 a; uint2 b;
    *reinterpret_cast<__half2*>(&a.x) = __floats2half2_rn(out[0], out[1]);
    *reinterpret_cast<__half2*>(&a.y) = __floats2half2_rn(out[2], out[3]);
    *reinterpret_cast<__half2*>(&a.z) = __floats2half2_rn(out[4], out[5]);
    *reinterpret_cast<__half2*>(&a.w) = __floats2half2_rn(out[6], out[7]);
    *reinterpret_cast<__half2*>(&b.x) = __floats2half2_rn(out[8], out[9]);
    *reinterpret_cast<__half2*>(&b.y) = __floats2half2_rn(out[10], out[11]);
    *reinterpret_cast<uint4*>(r) = a;
    *reinterpret_cast<uint2*>(r + 8) = b;
}

// ---------------- CSR build ----------------

__global__ void k_degx(const int* __restrict__ ei, const float* __restrict__ x) {
    int e = blockIdx.x * blockDim.x + threadIdx.x;
    if (e < N_EDGES) atomicAdd(&g_deg[ei[N_EDGES + e]], 1);
    if (e < N_NODES) {
        g_xp[e] = make_float4(x[3 * e], x[3 * e + 1], x[3 * e + 2], 0.f);
    }
}

// local exclusive scan: 1024 blocks x 1024 elements (256 thr x 4); re-zeroes g_deg
__global__ void k_scanA() {
    __shared__ int sh[256];
    int t = threadIdx.x;
    int base = blockIdx.x * 1024 + t * 4;
    int4 d = *reinterpret_cast<int4*>(&g_deg[base]);
    *reinterpret_cast<int4*>(&g_deg[base]) = make_int4(0, 0, 0, 0);
    int s1 = d.x + d.y, s2 = s1 + d.z, tot = s2 + d.w;
    sh[t] = tot;
    __syncthreads();
#pragma unroll
    for (int o = 1; o < 256; o <<= 1) {
        int v = (t >= o) ? sh[t - o] : 0;
        __syncthreads();
        sh[t] += v;
        __syncthreads();
    }
    int excl = sh[t] - tot;
    g_off[base + 0] = excl;
    g_off[base + 1] = excl + d.x;
    g_off[base + 2] = excl + s1;
    g_off[base + 3] = excl + s2;
    if (t == 255) g_bsum[blockIdx.x] = sh[255];
}

// finalize offsets; block 0 re-zeroes g_stats
__global__ void k_scanB() {
    __shared__ int sred[9];
    int t = threadIdx.x;
    if (blockIdx.x == 0 && t < STATS_LEN) g_stats[t] = 0.f;
    int q = blockIdx.x >> 2;
    int4 v = *reinterpret_cast<int4*>(&g_bsum[t * 4]);
    int j0 = t * 4;
    int s = (j0 + 0 < q ? v.x : 0) + (j0 + 1 < q ? v.y : 0)
          + (j0 + 2 < q ? v.z : 0) + (j0 + 3 < q ? v.w : 0);
#pragma unroll
    for (int o = 16; o; o >>= 1) s += __shfl_xor_sync(0xffffffffu, s, o);
    if ((t & 31) == 0) sred[t >> 5] = s;
    __syncthreads();
    if (t == 0) {
        int r0 = 0;
#pragma unroll
        for (int w = 0; w < 8; w++) r0 += sred[w];
        sred[8] = r0;
    }
    __syncthreads();
    int S = sred[8];
    int i = blockIdx.x * 256 + t;
    int val = g_off[i] + S;
    g_off[i] = val;
    g_cur[i] = val;
    if (i == 0) g_off[N_NODES] = N_EDGES;
}

__global__ void k_place(const int* __restrict__ ei) {
    int e = blockIdx.x * blockDim.x + threadIdx.x;
    if (e >= N_EDGES) return;
    int s = ei[e];
    int d = ei[N_EDGES + e];
    int p = atomicAdd(&g_cur[d], 1);
    g_srt[p] = s;
}

// ---------------- layer 1: float4-packed x gather (1 LDG/neighbor) ----------------
__global__ void k_node1f(const float* __restrict__ Wl1, const float* __restrict__ Wr1,
                         const float* __restrict__ b1) {
    __shared__ float sWl[36], sWr[36], sb[12], sSum[24];
    int t = threadIdx.x;
    if (t < 36) { sWl[t] = Wl1[t]; sWr[t] = Wr1[t]; }
    if (t < 12) sb[t] = b1[t];
    if (t < 24) sSum[t] = 0.f;
    __syncthreads();
    int i = blockIdx.x * blockDim.x + t;
    int beg = g_off[i], end = g_off[i + 1];
    float a0 = 0.f, a1 = 0.f, a2 = 0.f;
    int p = beg;
    for (; p + 2 <= end; p += 2) {
        int s0 = __ldg(&g_srt[p]), s1 = __ldg(&g_srt[p + 1]);
        float4 u = __ldg(&g_xp[s0]);
        float4 w = __ldg(&g_xp[s1]);
        a0 += u.x + w.x; a1 += u.y + w.y; a2 += u.z + w.z;
    }
    if (p < end) {
        float4 u = __ldg(&g_xp[__ldg(&g_srt[p])]);
        a0 += u.x; a1 += u.y; a2 += u.z;
    }
    int dg = end - beg;
    float inv = dg > 0 ? 1.f / (float)dg : 0.f;
    float m0 = a0 * inv, m1 = a1 * inv, m2 = a2 * inv;
    float4 xs = g_xp[i];
    float out[12];
#pragma unroll
    for (int k = 0; k < 12; k++) {
        float v = sb[k] + m0 * sWl[3 * k] + m1 * sWl[3 * k + 1] + m2 * sWl[3 * k + 2]
                        + xs.x * sWr[3 * k] + xs.y * sWr[3 * k + 1] + xs.z * sWr[3 * k + 2];
        out[k] = fmaxf(v, 0.f);
    }
    float4* hp = reinterpret_cast<float4*>(g_hA + (size_t)i * 12);
    hp[0] = make_float4(out[0], out[1], out[2], out[3]);
    hp[1] = make_float4(out[4], out[5], out[6], out[7]);
    hp[2] = make_float4(out[8], out[9], out[10], out[11]);
    storeH(g_hHA, i, out);
#pragma unroll
    for (int k = 0; k < 12; k++) {
        float s = out[k], q = out[k] * out[k];
        warpsum(s); warpsum(q);
        if ((t & 31) == 0) { atomicAdd(&sSum[k], s); atomicAdd(&sSum[12 + k], q); }
    }
    __syncthreads();
    if (t < 24) atomicAdd(&g_stats[t], sSum[t]);
}

// ---------------- layers 2..8: fp16 gather, 4-neighbor batched loads ----------------
template <int MODE>
__global__ void k_nodef(int in_sel, int out_sel,
                        const float* __restrict__ Wl, const float* __restrict__ Wr,
                        const float* __restrict__ bias,
                        const float* __restrict__ bng, const float* __restrict__ bnb,
                        int sin_off, int sout_off,
                        const float* __restrict__ linW, const float* __restrict__ linb) {
    const float*  h_in  = bufptr(in_sel);
    const __half* hH_in = bufptrH(in_sel);
    float*  h_out  = bufptr(out_sel);
    __half* hH_out = bufptrH(out_sel);
    __shared__ float sWl[144], sWr[144], sb[12], sa[12], sc[12], sSum[24], sLW[36], sLB[6];
    int t = threadIdx.x;
    if (t < 144) { sWl[t] = Wl[t]; sWr[t] = Wr[t]; }
    if (t < 12) {
        sb[t] = bias[t];
        float mean = g_stats[sin_off + t] * (1.f / N_NODES);
        float var  = g_stats[sin_off + 12 + t] * (1.f / N_NODES) - mean * mean;
        float a = bng[t] * rsqrtf(var + EPSV);
        sa[t] = a;
        sc[t] = bnb[t] - mean * a;
    }
    if (t < 24) sSum[t] = 0.f;
    if (MODE == 1) {
        if (t < 36) sLW[t] = linW[t];
        if (t < 6)  sLB[t] = linb[t];
    }
    __syncthreads();
    int i = blockIdx.x * blockDim.x + t;
    int beg = g_off[i], end = g_off[i + 1];
    float acc[12];
#pragma unroll
    for (int j = 0; j < 12; j++) acc[j] = 0.f;

    int p = beg;
    // 4-neighbor batch: issue all 8 row loads before any conversion/accumulation
    for (; p + 4 <= end; p += 4) {
        int s0 = __ldg(&g_srt[p]);
        int s1 = __ldg(&g_srt[p + 1]);
        int s2 = __ldg(&g_srt[p + 2]);
        int s3 = __ldg(&g_srt[p + 3]);
        const __half* r0 = hH_in + ((size_t)s0 << 4);
        const __half* r1 = hH_in + ((size_t)s1 << 4);
        const __half* r2 = hH_in + ((size_t)s2 << 4);
        const __half* r3 = hH_in + ((size_t)s3 << 4);
        uint4 a0 = __ldg(reinterpret_cast<const uint4*>(r0));
        uint4 a1 = __ldg(reinterpret_cast<const uint4*>(r1));
        uint4 a2 = __ldg(reinterpret_cast<const uint4*>(r2));
        uint4 a3 = __ldg(reinterpret_cast<const uint4*>(r3));
        uint2 b0 = __ldg(reinterpret_cast<const uint2*>(r0 + 8));
        uint2 b1 = __ldg(reinterpret_cast<const uint2*>(r1 + 8));
        uint2 b2 = __ldg(reinterpret_cast<const uint2*>(r2 + 8));
        uint2 b3 = __ldg(reinterpret_cast<const uint2*>(r3 + 8));
        accH(acc, a0, b0);
        accH(acc, a1, b1);
        accH(acc, a2, b2);
        accH(acc, a3, b3);
    }
    if (p + 2 <= end) {
        int s0 = __ldg(&g_srt[p]);
        int s1 = __ldg(&g_srt[p + 1]);
        const __half* r0 = hH_in + ((size_t)s0 << 4);
        const __half* r1 = hH_in + ((size_t)s1 << 4);
        uint4 a0 = __ldg(reinterpret_cast<const uint4*>(r0));
        uint4 a1 = __ldg(reinterpret_cast<const uint4*>(r1));
        uint2 b0 = __ldg(reinterpret_cast<const uint2*>(r0 + 8));
        uint2 b1 = __ldg(reinterpret_cast<const uint2*>(r1 + 8));
        accH(acc, a0, b0);
        accH(acc, a1, b1);
        p += 2;
    }
    if (p < end) {
        const __half* r0 = hH_in + ((size_t)__ldg(&g_srt[p]) << 4);
        uint4 a0 = __ldg(reinterpret_cast<const uint4*>(r0));
        uint2 b0 = __ldg(reinterpret_cast<const uint2*>(r0 + 8));
        accH(acc, a0, b0);
    }

    const float4* hp = reinterpret_cast<const float4*>(h_in + (size_t)i * 12);
    float4 h0 = hp[0], h1 = hp[1], h2 = hp[2];
    float hv[12] = {h0.x, h0.y, h0.z, h0.w, h1.x, h1.y, h1.z, h1.w, h2.x, h2.y, h2.z, h2.w};
    int dg = end - beg;
    float gate = dg > 0 ? 1.f : 0.f;
    float inv  = dg > 0 ? 1.f / (float)dg : 0.f;
    float m[12], hb[12];
#pragma unroll
    for (int j = 0; j < 12; j++) {
        m[j]  = acc[j] * inv * sa[j] + sc[j] * gate;   // bn(mean) fold; isolated -> 0
        hb[j] = hv[j] * sa[j] + sc[j];
    }
    float out[12];
#pragma unroll
    for (int k = 0; k < 12; k++) {
        float v = sb[k];
#pragma unroll
        for (int j = 0; j < 12; j++) v += m[j] * sWl[12 * k + j] + hb[j] * sWr[12 * k + j];
        out[k] = fmaxf(v, 0.f);
    }
    float4* op = reinterpret_cast<float4*>(h_out + (size_t)i * 12);
    op[0] = make_float4(out[0], out[1], out[2], out[3]);
    op[1] = make_float4(out[4], out[5], out[6], out[7]);
    op[2] = make_float4(out[8], out[9], out[10], out[11]);
    storeH(hH_out, i, out);
    if (MODE == 0) {
#pragma unroll
        for (int k = 0; k < 12; k++) {
            float s = out[k], q = out[k] * out[k];
            warpsum(s); warpsum(q);
            if ((t & 31) == 0) { atomicAdd(&sSum[k], s); atomicAdd(&sSum[12 + k], q); }
        }
        __syncthreads();
        if (t < 24) atomicAdd(&g_stats[sout_off + t], sSum[t]);
    } else {
#pragma unroll
        for (int k = 0; k < 6; k++) {
            float za = sLB[k], zb = sLB[k];
#pragma unroll
            for (int j = 0; j < 6; j++) { za += out[j] * sLW[6 * k + j]; zb += out[6 + j] * sLW[6 * k + j]; }
            float s = za + zb, q = za * za + zb * zb;
            warpsum(s); warpsum(q);
            if ((t & 31) == 0) { atomicAdd(&sSum[k], s); atomicAdd(&sSum[6 + k], q); }
        }
        __syncthreads();
        if (t < 12) atomicAdd(&g_stats[sout_off + t], sSum[t]);
    }
}

// ---------------- head (all fp32) ----------------
template <int PASS>
__global__ void k_head(int in_sel, int out_sel,
                       const float* __restrict__ linW, const float* __restrict__ linb,
                       const float* __restrict__ g6, const float* __restrict__ b6,
                       int sin_off, int sout_off,
                       const float* __restrict__ oW, const float* __restrict__ ob,
                       float* __restrict__ outp) {
    const float* h_in = bufptr(in_sel);
    float* h_out = bufptr(out_sel);
    __shared__ float sLW[36], sLB[6], sa[6], sc[6], sSum[12], sOW[7];
    int t = threadIdx.x;
    if (t < 36) sLW[t] = linW[t];
    if (t < 6) {
        sLB[t] = linb[t];
        const float invM = 1.f / (2.f * N_NODES);
        float mean = g_stats[sin_off + t] * invM;
        float var  = g_stats[sin_off + 6 + t] * invM - mean * mean;
        float a = g6[t] * rsqrtf(var + EPSV);
        sa[t] = a;
        sc[t] = b6[t] - mean * a;
    }
    if (t < 12) sSum[t] = 0.f;
    if (PASS == 3) { if (t < 6) sOW[t] = oW[t]; if (t == 6) sOW[6] = ob[0]; }
    __syncthreads();
    int i = blockIdx.x * blockDim.x + t;
    const float4* hp = reinterpret_cast<const float4*>(h_in + (size_t)i * 12);
    float4 h0 = hp[0], h1 = hp[1], h2 = hp[2];
    float hv[12] = {h0.x, h0.y, h0.z, h0.w, h1.x, h1.y, h1.z, h1.w, h2.x, h2.y, h2.z, h2.w};
    float r[12];
#pragma unroll
    for (int half = 0; half < 2; half++) {
#pragma unroll
        for (int k = 0; k < 6; k++) {
            float z = sLB[k];
#pragma unroll
            for (int j = 0; j < 6; j++) z += hv[6 * half + j] * sLW[6 * k + j];
            r[6 * half + k] = fmaxf(z * sa[k] + sc[k], 0.f);
        }
    }
    if (PASS < 3) {
        float4* op = reinterpret_cast<float4*>(h_out + (size_t)i * 12);
        op[0] = make_float4(r[0], r[1], r[2], r[3]);
        op[1] = make_float4(r[4], r[5], r[6], r[7]);
        op[2] = make_float4(r[8], r[9], r[10], r[11]);
#pragma unroll
        for (int k = 0; k < 6; k++) {
            float za = sLB[k], zb = sLB[k];
#pragma unroll
            for (int j = 0; j < 6; j++) { za += r[j] * sLW[6 * k + j]; zb += r[6 + j] * sLW[6 * k + j]; }
            float s = za + zb, q = za * za + zb * zb;
            warpsum(s); warpsum(q);
            if ((t & 31) == 0) { atomicAdd(&sSum[k], s); atomicAdd(&sSum[6 + k], q); }
        }
        __syncthreads();
        if (t < 12) atomicAdd(&g_stats[sout_off + t], sSum[t]);
    } else {
        float oa = sOW[6], obv = sOW[6];
#pragma unroll
        for (int j = 0; j < 6; j++) { oa += r[j] * sOW[j]; obv += r[6 + j] * sOW[j]; }
        outp[2 * i]     = 1.f / (1.f + expf(-oa));
        outp[2 * i + 1] = 1.f / (1.f + expf(-obv));
    }
}

// ---------------- launch ----------------
extern "C" void kernel_launch(void* const* d_in, const int* in_sizes, int n_in,
                              void* d_out, int out_size) {
    const float* x    = (const float*)d_in[0];
    const int*   ei   = (const int*)d_in[1];
    const float* Wl1  = (const float*)d_in[2];
    const float* Wr1  = (const float*)d_in[3];
    const float* b1   = (const float*)d_in[4];
    const float* Wl   = (const float*)d_in[5];
    const float* Wr   = (const float*)d_in[6];
    const float* bb   = (const float*)d_in[7];
    const float* bng  = (const float*)d_in[8];
    const float* bnb  = (const float*)d_in[9];
    const float* linW = (const float*)d_in[10];
    const float* linb = (const float*)d_in[11];
    const float* g6   = (const float*)d_in[12];
    const float* b6   = (const float*)d_in[13];
    const float* oW   = (const float*)d_in[14];
    const float* ob   = (const float*)d_in[15];
    float* outp = (float*)d_out;

    const int EB = N_EDGES / 256;   // 16384
    const int NB = N_NODES / 256;   // 4096

    // CSR build (g_deg/g_stats zero at entry: load-time init or fused re-zeroing)
    k_degx<<<EB, 256>>>(ei, x);
    k_scanA<<<1024, 256>>>();       // also re-zeroes g_deg for next call
    k_scanB<<<NB, 256>>>();         // block 0 also re-zeroes g_stats
    k_place<<<EB, 256>>>(ei);

    // conv1 -> hA + fp16 mirror, stats slot 0
    k_node1f<<<NB, 256>>>(Wl1, Wr1, b1);

    int in_sel = 0, out_sel = 1;
    for (int i = 0; i < 7; i++) {
        int sin_off = 24 * i;
        if (i < 6) {
            k_nodef<0><<<NB, 256>>>(in_sel, out_sel, Wl + 144 * i, Wr + 144 * i, bb + 12 * i,
                                    bng + 12 * i, bnb + 12 * i, sin_off, 24 * (i + 1),
                                    linW, linb);
        } else {
            k_nodef<1><<<NB, 256>>>(in_sel, out_sel, Wl + 144 * i, Wr + 144 * i, bb + 12 * i,
                                    bng + 12 * i, bnb + 12 * i, sin_off, 7 * 24,
                                    linW, linb);
        }
        int tmp = in_sel; in_sel = out_sel; out_sel = tmp;
    }
    // conv8 output in hB (in_sel==1). Head: hB -> hA -> hB -> out.
    k_head<1><<<NB, 256>>>(1, 0, linW, linb, g6, b6, 168, 180, oW, ob, outp);
    k_head<2><<<NB, 256>>>(0, 1, linW, linb, g6, b6, 180, 192, oW, ob, outp);
    k_head<3><<<NB, 256>>>(1, 0, linW, linb, g6, b6, 192, 0, oW, ob, outp);
}

// round 10
// speedup vs baseline: 1.0556x; 1.0556x over previous
#include <cuda_runtime.h>
#include <cuda_fp16.h>
#include <math.h>

#define N_NODES 1048576
#define N_EDGES 4194304
#define EPSV 1e-5f
#define STATS_LEN (7*24 + 3*12)

// ---------------- scratch (static device globals; zero-init at load) ----------------
__device__ float  g_hA[N_NODES * 12];
__device__ float  g_hB[N_NODES * 12];
__device__ __half g_hHA[N_NODES * 16];   // fp16 mirror (32B rows) for gather
__device__ __half g_hHB[N_NODES * 16];
__device__ float4 g_xp[N_NODES];         // x packed to float4
__device__ int    g_deg[N_NODES];        // zeroed by k_scanA for next call
__device__ int    g_off[N_NODES + 1];
__device__ int    g_cur[N_NODES];
__device__ int    g_bsum[1024];
__device__ int    g_srt[N_EDGES];        // src ids grouped by dst (CSR adjacency)
__device__ float  g_stats[STATS_LEN];    // zeroed by k_scanB for next call

__device__ __forceinline__ float*  bufptr(int s)  { return s == 0 ? g_hA : g_hB; }
__device__ __forceinline__ __half* bufptrH(int s) { return s == 0 ? g_hHA : g_hHB; }

__device__ __forceinline__ void warpsum(float& v) {
#pragma unroll
    for (int o = 16; o; o >>= 1) v += __shfl_xor_sync(0xffffffffu, v, o);
}

// fp16 gather: 24 useful bytes in 2 loads (row is 32B aligned, single 128B line).
// __ldg keeps these L2-cached: the mirror is the high-reuse random working set.
__device__ __forceinline__ void gathH(float* acc, const __half* hH, int s) {
    const __half* r = hH + ((size_t)s << 4);
    uint4 a = __ldg(reinterpret_cast<const uint4*>(r));
    uint2 b = __ldg(reinterpret_cast<const uint2*>(r + 8));
    float2 f;
    f = __half22float2(*reinterpret_cast<__half2*>(&a.x)); acc[0] += f.x; acc[1] += f.y;
    f = __half22float2(*reinterpret_cast<__half2*>(&a.y)); acc[2] += f.x; acc[3] += f.y;
    f = __half22float2(*reinterpret_cast<__half2*>(&a.z)); acc[4] += f.x; acc[5] += f.y;
    f = __half22float2(*reinterpret_cast<__half2*>(&a.w)); acc[6] += f.x; acc[7] += f.y;
    f = __half22float2(*reinterpret_cast<__half2*>(&b.x)); acc[8] += f.x; acc[9] += f.y;
    f = __half22float2(*reinterpret_cast<__half2*>(&b.y)); acc[10] += f.x; acc[11] += f.y;
}

__device__ __forceinline__ void storeH(__half* hH, int i, const float* out) {
    __half* r = hH + ((size_t)i << 4);
    uint4 a; uint2 b;
    *reinterpret_cast<__half2*>(&a.x) = __floats2half2_rn(out[0], out[1]);
    *reinterpret_cast<__half2*>(&a.y) = __floats2half2_rn(out[2], out[3]);
    *reinterpret_cast<__half2*>(&a.z) = __floats2half2_rn(out[4], out[5]);
    *reinterpret_cast<__half2*>(&a.w) = __floats2half2_rn(out[6], out[7]);
    *reinterpret_cast<__half2*>(&b.x) = __floats2half2_rn(out[8], out[9]);
    *reinterpret_cast<__half2*>(&b.y) = __floats2half2_rn(out[10], out[11]);
    *reinterpret_cast<uint4*>(r) = a;
    *reinterpret_cast<uint2*>(r + 8) = b;
}

// ---------------- CSR build ----------------

// degree histogram + x packing. ei is single-use here: streaming loads.
__global__ void k_degx(const int* __restrict__ ei, const float* __restrict__ x) {
    int e = blockIdx.x * blockDim.x + threadIdx.x;
    if (e < N_EDGES) atomicAdd(&g_deg[__ldcs(&ei[N_EDGES + e])], 1);
    if (e < N_NODES) {
        g_xp[e] = make_float4(__ldcs(&x[3 * e]), __ldcs(&x[3 * e + 1]),
                              __ldcs(&x[3 * e + 2]), 0.f);
    }
}

// local exclusive scan: 1024 blocks x 1024 elements (256 thr x 4); re-zeroes g_deg
__global__ void k_scanA() {
    __shared__ int sh[256];
    int t = threadIdx.x;
    int base = blockIdx.x * 1024 + t * 4;
    int4 d = *reinterpret_cast<int4*>(&g_deg[base]);
    *reinterpret_cast<int4*>(&g_deg[base]) = make_int4(0, 0, 0, 0);
    int s1 = d.x + d.y, s2 = s1 + d.z, tot = s2 + d.w;
    sh[t] = tot;
    __syncthreads();
#pragma unroll
    for (int o = 1; o < 256; o <<= 1) {
        int v = (t >= o) ? sh[t - o] : 0;
        __syncthreads();
        sh[t] += v;
        __syncthreads();
    }
    int excl = sh[t] - tot;
    g_off[base + 0] = excl;
    g_off[base + 1] = excl + d.x;
    g_off[base + 2] = excl + s1;
    g_off[base + 3] = excl + s2;
    if (t == 255) g_bsum[blockIdx.x] = sh[255];
}

// finalize offsets; block 0 re-zeroes g_stats
__global__ void k_scanB() {
    __shared__ int sred[9];
    int t = threadIdx.x;
    if (blockIdx.x == 0 && t < STATS_LEN) g_stats[t] = 0.f;
    int q = blockIdx.x >> 2;
    int4 v = *reinterpret_cast<int4*>(&g_bsum[t * 4]);
    int j0 = t * 4;
    int s = (j0 + 0 < q ? v.x : 0) + (j0 + 1 < q ? v.y : 0)
          + (j0 + 2 < q ? v.z : 0) + (j0 + 3 < q ? v.w : 0);
#pragma unroll
    for (int o = 16; o; o >>= 1) s += __shfl_xor_sync(0xffffffffu, s, o);
    if ((t & 31) == 0) sred[t >> 5] = s;
    __syncthreads();
    if (t == 0) {
        int r0 = 0;
#pragma unroll
        for (int w = 0; w < 8; w++) r0 += sred[w];
        sred[8] = r0;
    }
    __syncthreads();
    int S = sred[8];
    int i = blockIdx.x * 256 + t;
    int val = g_off[i] + S;
    g_off[i] = val;
    g_cur[i] = val;
    if (i == 0) g_off[N_NODES] = N_EDGES;
}

__global__ void k_place(const int* __restrict__ ei) {
    int e = blockIdx.x * blockDim.x + threadIdx.x;
    if (e >= N_EDGES) return;
    int s = __ldcs(&ei[e]);
    int d = __ldcs(&ei[N_EDGES + e]);
    int p = atomicAdd(&g_cur[d], 1);
    g_srt[p] = s;
}

// ---------------- layer 1: float4-packed x gather (1 LDG/neighbor) ----------------
__global__ void k_node1f(const float* __restrict__ Wl1, const float* __restrict__ Wr1,
                         const float* __restrict__ b1) {
    __shared__ float sWl[36], sWr[36], sb[12], sSum[24];
    int t = threadIdx.x;
    if (t < 36) { sWl[t] = Wl1[t]; sWr[t] = Wr1[t]; }
    if (t < 12) sb[t] = b1[t];
    if (t < 24) sSum[t] = 0.f;
    __syncthreads();
    int i = blockIdx.x * blockDim.x + t;
    int beg = g_off[i], end = g_off[i + 1];
    float a0 = 0.f, a1 = 0.f, a2 = 0.f;
    int p = beg;
    for (; p + 2 <= end; p += 2) {
        int s0 = __ldg(&g_srt[p]), s1 = __ldg(&g_srt[p + 1]);
        float4 u = __ldg(&g_xp[s0]);
        float4 w = __ldg(&g_xp[s1]);
        a0 += u.x + w.x; a1 += u.y + w.y; a2 += u.z + w.z;
    }
    if (p < end) {
        float4 u = __ldg(&g_xp[__ldg(&g_srt[p])]);
        a0 += u.x; a1 += u.y; a2 += u.z;
    }
    int dg = end - beg;
    float inv = dg > 0 ? 1.f / (float)dg : 0.f;
    float m0 = a0 * inv, m1 = a1 * inv, m2 = a2 * inv;
    float4 xs = __ldg(&g_xp[i]);
    float out[12];
#pragma unroll
    for (int k = 0; k < 12; k++) {
        float v = sb[k] + m0 * sWl[3 * k] + m1 * sWl[3 * k + 1] + m2 * sWl[3 * k + 2]
                        + xs.x * sWr[3 * k] + xs.y * sWr[3 * k + 1] + xs.z * sWr[3 * k + 2];
        out[k] = fmaxf(v, 0.f);
    }
    // fp32 h is single-use streaming traffic: keep it out of L2 (evict-first)
    float4* hp = reinterpret_cast<float4*>(g_hA + (size_t)i * 12);
    __stcs(hp + 0, make_float4(out[0], out[1], out[2], out[3]));
    __stcs(hp + 1, make_float4(out[4], out[5], out[6], out[7]));
    __stcs(hp + 2, make_float4(out[8], out[9], out[10], out[11]));
    storeH(g_hHA, i, out);
#pragma unroll
    for (int k = 0; k < 12; k++) {
        float s = out[k], q = out[k] * out[k];
        warpsum(s); warpsum(q);
        if ((t & 31) == 0) { atomicAdd(&sSum[k], s); atomicAdd(&sSum[12 + k], q); }
    }
    __syncthreads();
    if (t < 24) atomicAdd(&g_stats[t], sSum[t]);
}

// ---------------- layers 2..8: fp16 gather (2 LDG/neighbor), fp32 everywhere else ----
// fp32 self-row reads and h_out writes use streaming hints so the fp16 mirrors
// + srt stay L2-resident for the random gathers.
template <int MODE>
__global__ void k_nodef(int in_sel, int out_sel,
                        const float* __restrict__ Wl, const float* __restrict__ Wr,
                        const float* __restrict__ bias,
                        const float* __restrict__ bng, const float* __restrict__ bnb,
                        int sin_off, int sout_off,
                        const float* __restrict__ linW, const float* __restrict__ linb) {
    const float*  h_in  = bufptr(in_sel);
    const __half* hH_in = bufptrH(in_sel);
    float*  h_out  = bufptr(out_sel);
    __half* hH_out = bufptrH(out_sel);
    __shared__ float sWl[144], sWr[144], sb[12], sa[12], sc[12], sSum[24], sLW[36], sLB[6];
    int t = threadIdx.x;
    if (t < 144) { sWl[t] = Wl[t]; sWr[t] = Wr[t]; }
    if (t < 12) {
        sb[t] = bias[t];
        float mean = g_stats[sin_off + t] * (1.f / N_NODES);
        float var  = g_stats[sin_off + 12 + t] * (1.f / N_NODES) - mean * mean;
        float a = bng[t] * rsqrtf(var + EPSV);
        sa[t] = a;
        sc[t] = bnb[t] - mean * a;
    }
    if (t < 24) sSum[t] = 0.f;
    if (MODE == 1) {
        if (t < 36) sLW[t] = linW[t];
        if (t < 6)  sLB[t] = linb[t];
    }
    __syncthreads();
    int i = blockIdx.x * blockDim.x + t;
    int beg = g_off[i], end = g_off[i + 1];
    float acc[12];
#pragma unroll
    for (int j = 0; j < 12; j++) acc[j] = 0.f;
    int p = beg;
    for (; p + 2 <= end; p += 2) {
        int s0 = __ldg(&g_srt[p]), s1 = __ldg(&g_srt[p + 1]);
        gathH(acc, hH_in, s0);
        gathH(acc, hH_in, s1);
    }
    if (p < end) gathH(acc, hH_in, __ldg(&g_srt[p]));

    const float4* hp = reinterpret_cast<const float4*>(h_in + (size_t)i * 12);
    float4 h0 = __ldcs(hp + 0), h1 = __ldcs(hp + 1), h2 = __ldcs(hp + 2);
    float hv[12] = {h0.x, h0.y, h0.z, h0.w, h1.x, h1.y, h1.z, h1.w, h2.x, h2.y, h2.z, h2.w};
    int dg = end - beg;
    float gate = dg > 0 ? 1.f : 0.f;
    float inv  = dg > 0 ? 1.f / (float)dg : 0.f;
    float m[12], hb[12];
#pragma unroll
    for (int j = 0; j < 12; j++) {
        m[j]  = acc[j] * inv * sa[j] + sc[j] * gate;   // bn(mean) fold; isolated -> 0
        hb[j] = hv[j] * sa[j] + sc[j];
    }
    float out[12];
#pragma unroll
    for (int k = 0; k < 12; k++) {
        float v = sb[k];
#pragma unroll
        for (int j = 0; j < 12; j++) v += m[j] * sWl[12 * k + j] + hb[j] * sWr[12 * k + j];
        out[k] = fmaxf(v, 0.f);
    }
    float4* op = reinterpret_cast<float4*>(h_out + (size_t)i * 12);
    __stcs(op + 0, make_float4(out[0], out[1], out[2], out[3]));
    __stcs(op + 1, make_float4(out[4], out[5], out[6], out[7]));
    __stcs(op + 2, make_float4(out[8], out[9], out[10], out[11]));
    storeH(hH_out, i, out);
    if (MODE == 0) {
#pragma unroll
        for (int k = 0; k < 12; k++) {
            float s = out[k], q = out[k] * out[k];
            warpsum(s); warpsum(q);
            if ((t & 31) == 0) { atomicAdd(&sSum[k], s); atomicAdd(&sSum[12 + k], q); }
        }
        __syncthreads();
        if (t < 24) atomicAdd(&g_stats[sout_off + t], sSum[t]);
    } else {
#pragma unroll
        for (int k = 0; k < 6; k++) {
            float za = sLB[k], zb = sLB[k];
#pragma unroll
            for (int j = 0; j < 6; j++) { za += out[j] * sLW[6 * k + j]; zb += out[6 + j] * sLW[6 * k + j]; }
            float s = za + zb, q = za * za + zb * zb;
            warpsum(s); warpsum(q);
            if ((t & 31) == 0) { atomicAdd(&sSum[k], s); atomicAdd(&sSum[6 + k], q); }
        }
        __syncthreads();
        if (t < 12) atomicAdd(&g_stats[sout_off + t], sSum[t]);
    }
}

// ---------------- head (all fp32, streaming) ----------------
template <int PASS>
__global__ void k_head(int in_sel, int out_sel,
                       const float* __restrict__ linW, const float* __restrict__ linb,
                       const float* __restrict__ g6, const float* __restrict__ b6,
                       int sin_off, int sout_off,
                       const float* __restrict__ oW, const float* __restrict__ ob,
                       float* __restrict__ outp) {
    const float* h_in = bufptr(in_sel);
    float* h_out = bufptr(out_sel);
    __shared__ float sLW[36], sLB[6], sa[6], sc[6], sSum[12], sOW[7];
    int t = threadIdx.x;
    if (t < 36) sLW[t] = linW[t];
    if (t < 6) {
        sLB[t] = linb[t];
        const float invM = 1.f / (2.f * N_NODES);
        float mean = g_stats[sin_off + t] * invM;
        float var  = g_stats[sin_off + 6 + t] * invM - mean * mean;
        float a = g6[t] * rsqrtf(var + EPSV);
        sa[t] = a;
        sc[t] = b6[t] - mean * a;
    }
    if (t < 12) sSum[t] = 0.f;
    if (PASS == 3) { if (t < 6) sOW[t] = oW[t]; if (t == 6) sOW[6] = ob[0]; }
    __syncthreads();
    int i = blockIdx.x * blockDim.x + t;
    const float4* hp = reinterpret_cast<const float4*>(h_in + (size_t)i * 12);
    float4 h0 = __ldcs(hp + 0), h1 = __ldcs(hp + 1), h2 = __ldcs(hp + 2);
    float hv[12] = {h0.x, h0.y, h0.z, h0.w, h1.x, h1.y, h1.z, h1.w, h2.x, h2.y, h2.z, h2.w};
    float r[12];
#pragma unroll
    for (int half = 0; half < 2; half++) {
#pragma unroll
        for (int k = 0; k < 6; k++) {
            float z = sLB[k];
#pragma unroll
            for (int j = 0; j < 6; j++) z += hv[6 * half + j] * sLW[6 * k + j];
            r[6 * half + k] = fmaxf(z * sa[k] + sc[k], 0.f);
        }
    }
    if (PASS < 3) {
        float4* op = reinterpret_cast<float4*>(h_out + (size_t)i * 12);
        __stcs(op + 0, make_float4(r[0], r[1], r[2], r[3]));
        __stcs(op + 1, make_float4(r[4], r[5], r[6], r[7]));
        __stcs(op + 2, make_float4(r[8], r[9], r[10], r[11]));
#pragma unroll
        for (int k = 0; k < 6; k++) {
            float za = sLB[k], zb = sLB[k];
#pragma unroll
            for (int j = 0; j < 6; j++) { za += r[j] * sLW[6 * k + j]; zb += r[6 + j] * sLW[6 * k + j]; }
            float s = za + zb, q = za * za + zb * zb;
            warpsum(s); warpsum(q);
            if ((t & 31) == 0) { atomicAdd(&sSum[k], s); atomicAdd(&sSum[6 + k], q); }
        }
        __syncthreads();
        if (t < 12) atomicAdd(&g_stats[sout_off + t], sSum[t]);
    } else {
        float oa = sOW[6], obv = sOW[6];
#pragma unroll
        for (int j = 0; j < 6; j++) { oa += r[j] * sOW[j]; obv += r[6 + j] * sOW[j]; }
        outp[2 * i]     = 1.f / (1.f + expf(-oa));
        outp[2 * i + 1] = 1.f / (1.f + expf(-obv));
    }
}

// ---------------- launch ----------------
extern "C" void kernel_launch(void* const* d_in, const int* in_sizes, int n_in,
                              void* d_out, int out_size) {
    const float* x    = (const float*)d_in[0];
    const int*   ei   = (const int*)d_in[1];
    const float* Wl1  = (const float*)d_in[2];
    const float* Wr1  = (const float*)d_in[3];
    const float* b1   = (const float*)d_in[4];
    const float* Wl   = (const float*)d_in[5];
    const float* Wr   = (const float*)d_in[6];
    const float* bb   = (const float*)d_in[7];
    const float* bng  = (const float*)d_in[8];
    const float* bnb  = (const float*)d_in[9];
    const float* linW = (const float*)d_in[10];
    const float* linb = (const float*)d_in[11];
    const float* g6   = (const float*)d_in[12];
    const float* b6   = (const float*)d_in[13];
    const float* oW   = (const float*)d_in[14];
    const float* ob   = (const float*)d_in[15];
    float* outp = (float*)d_out;

    const int EB = N_EDGES / 256;   // 16384
    const int NB = N_NODES / 256;   // 4096

    // CSR build (g_deg/g_stats zero at entry: load-time init or fused re-zeroing)
    k_degx<<<EB, 256>>>(ei, x);
    k_scanA<<<1024, 256>>>();       // also re-zeroes g_deg for next call
    k_scanB<<<NB, 256>>>();         // block 0 also re-zeroes g_stats
    k_place<<<EB, 256>>>(ei);

    // conv1 -> hA + fp16 mirror, stats slot 0
    k_node1f<<<NB, 256>>>(Wl1, Wr1, b1);

    int in_sel = 0, out_sel = 1;
    for (int i = 0; i < 7; i++) {
        int sin_off = 24 * i;
        if (i < 6) {
            k_nodef<0><<<NB, 256>>>(in_sel, out_sel, Wl + 144 * i, Wr + 144 * i, bb + 12 * i,
                                    bng + 12 * i, bnb + 12 * i, sin_off, 24 * (i + 1),
                                    linW, linb);
        } else {
            k_nodef<1><<<NB, 256>>>(in_sel, out_sel, Wl + 144 * i, Wr + 144 * i, bb + 12 * i,
                                    bng + 12 * i, bnb + 12 * i, sin_off, 7 * 24,
                                    linW, linb);
        }
        int tmp = in_sel; in_sel = out_sel; out_sel = tmp;
    }
    // conv8 output in hB (in_sel==1). Head: hB -> hA -> hB -> out.
    k_head<1><<<NB, 256>>>(1, 0, linW, linb, g6, b6, 168, 180, oW, ob, outp);
    k_head<2><<<NB, 256>>>(0, 1, linW, linb, g6, b6, 180, 192, oW, ob, outp);
    k_head<3><<<NB, 256>>>(1, 0, linW, linb, g6, b6, 192, 0, oW, ob, outp);
}